// round 15
// baseline (speedup 1.0000x reference)
#include <cuda_runtime.h>
#include <cuda_fp16.h>
#include <cstdint>

#define BATCH 8
#define C 64
#define H 224
#define W 224
#define E 768
#define PH 56
#define PW 56
#define HW (H*W)        // 50176
#define NPB (PH*PW)     // 3136 patches per batch
#define NP (BATCH*NPB)  // 25088 total patches
#define KDIM 1024       // C * 4 * 4

// ---------------- scratch (device globals: allocation-free) ----------------
__device__ __half g_tokensH[BATCH * HW * C];        // NHWC fp16 [b][h][w][c]
__device__ __half g_Vf[(size_t)NP * KDIM];          // [n][k] fp16
__device__ __half g_W2f[E * KDIM];                  // [m][k] fp16
__device__ float  g_params[NP * 4];                 // offx, offy, scx, scy

// ======================= PTX helpers (sm_100 base ISA only) ================
__device__ __forceinline__ uint32_t smem_u32(const void* p) {
    uint32_t a;
    asm("{ .reg .u64 t; cvta.to.shared.u64 t, %1; cvt.u32.u64 %0, t; }" : "=r"(a) : "l"(p));
    return a;
}
#define CP_ASYNC16(dst, src) \
    asm volatile("cp.async.cg.shared.global [%0], [%1], 16;" :: "r"(dst), "l"(src) : "memory")
#define CP_COMMIT() asm volatile("cp.async.commit_group;" ::: "memory")
#define CP_WAIT(n)  asm volatile("cp.async.wait_group %0;" :: "n"(n) : "memory")

#define LDSM_X4(r0, r1, r2, r3, addr) \
    asm volatile("ldmatrix.sync.aligned.m8n8.x4.shared.b16 {%0,%1,%2,%3}, [%4];" \
        : "=r"(r0), "=r"(r1), "=r"(r2), "=r"(r3) : "r"(addr))

#define MMA16816(d, a, b) \
    asm volatile("mma.sync.aligned.m16n8k16.row.col.f32.f16.f16.f32 " \
        "{%0,%1,%2,%3}, {%4,%5,%6,%7}, {%8,%9}, {%0,%1,%2,%3};" \
        : "+f"((d)[0]), "+f"((d)[1]), "+f"((d)[2]), "+f"((d)[3]) \
        : "r"((a)[0]), "r"((a)[1]), "r"((a)[2]), "r"((a)[3]), \
          "r"((b)[0]), "r"((b)[1]))

__device__ __forceinline__ uint32_t swz128(uint32_t off) {
    return off ^ ((off >> 3) & 0x70);
}

// ---------------------------------------------------------------------------
// Stage 1 (+0): per-patch params AND w2->fp16 conversion (fused: one launch).
// Channel loop unrolled 8-wide: 8 independent shfl-reduce chains in flight.
// ---------------------------------------------------------------------------
__global__ void params_kernel(const float* __restrict__ x,
                              const float* __restrict__ w_off,
                              const float* __restrict__ b_off,
                              const float* __restrict__ w_sc,
                              const float* __restrict__ b_sc,
                              const float* __restrict__ w2) {
    __shared__ float wox[C], woy[C], wsx[C], wsy[C];
    int b = blockIdx.y;
    int i = blockIdx.x;              // patch row 0..55
    int tid = threadIdx.x;           // 0..255; active < 224

    // folded wsplit: convert w2 to fp16 (grid-strided)
    {
        int gtid = (blockIdx.y * gridDim.x + blockIdx.x) * 256 + tid;
        int nthreads = gridDim.x * gridDim.y * 256;
        for (int idx = gtid; idx < E * KDIM / 2; idx += nthreads) {
            float2 v = ((const float2*)w2)[idx];
            ((__half2*)g_W2f)[idx] = __floats2half2_rn(v.x, v.y);
        }
    }

    if (tid < C) {
        wox[tid] = w_off[tid];
        woy[tid] = w_off[C + tid];
        wsx[tid] = w_sc[tid];
        wsy[tid] = w_sc[C + tid];
    }
    __syncthreads();

    const float* xrow = x + ((size_t)b * C) * HW + (size_t)(i * 4) * W;
    float aox = 0.f, aoy = 0.f, asx = 0.f, asy = 0.f;
    bool active = tid < 224;

    for (int c0 = 0; c0 < C; c0 += 8) {
        float s[8];
        #pragma unroll
        for (int u = 0; u < 8; ++u) {
            s[u] = 0.f;
            if (active) {
                const float* p = xrow + (size_t)(c0 + u) * HW + tid;
                s[u] = p[0] + p[W] + p[2 * W] + p[3 * W];
            }
        }
        #pragma unroll
        for (int u = 0; u < 8; ++u) s[u] += __shfl_xor_sync(0xffffffffu, s[u], 1);
        #pragma unroll
        for (int u = 0; u < 8; ++u) s[u] += __shfl_xor_sync(0xffffffffu, s[u], 2);
        #pragma unroll
        for (int u = 0; u < 8; ++u) {
            float g = s[u] * (1.0f / 16.0f);
            g = (g > 0.f) ? g : 0.01f * g;       // leaky relu
            int c = c0 + u;
            aox += g * wox[c];
            aoy += g * woy[c];
            asx += g * wsx[c];
            asy += g * wsy[c];
        }
    }

    if (active && (tid & 3) == 0) {
        int j = tid >> 2;                        // patch col 0..55
        int n = b * NPB + i * PW + j;
        g_params[n * 4 + 0] = (aox + b_off[0]) * (1.0f / 56.0f);
        g_params[n * 4 + 1] = (aoy + b_off[1]) * (1.0f / 56.0f);
        g_params[n * 4 + 2] = asx + b_sc[0];
        g_params[n * 4 + 3] = asy + b_sc[1];
    }
}

// ---------------------------------------------------------------------------
// Stage 2: tokens = 1x1 conv (64->64) + bias via fp16 mma.sync.
// ---------------------------------------------------------------------------
__global__ void __launch_bounds__(128) tokens_kernel(const float* __restrict__ x,
                                                     const float* __restrict__ w1,
                                                     const float* __restrict__ b1) {
    __shared__ __half Xs[64 * 64];   // [px][k], 128B rows, swizzled
    __shared__ __half W1s[64 * 64];  // [c][k],  128B rows, swizzled
    __shared__ __half Os[64 * 72];   // [px][c], pad-72 rows (conflict-free)
    __shared__ float b1s[C];

    int b = blockIdx.y;
    int px0 = blockIdx.x * 64;
    int tid = threadIdx.x;
    int wid = tid >> 5, lane = tid & 31;

    char* xb8 = (char*)Xs;
    char* wb8 = (char*)W1s;

    const float* xb = x + ((size_t)b * C) * HW + px0;
    for (int idx = tid; idx < 64 * 32; idx += 128) {
        int px = idx & 63, kp = idx >> 6;        // kp = pair of channels
        float v0 = xb[(size_t)(2 * kp)     * HW + px];
        float v1 = xb[(size_t)(2 * kp + 1) * HW + px];
        uint32_t off = (uint32_t)(px * 128 + kp * 4);
        *(__half2*)(xb8 + swz128(off)) = __floats2half2_rn(v0, v1);
    }
    for (int idx = tid; idx < 64 * 32; idx += 128) {
        int co = idx >> 5, cp = idx & 31;
        float2 wv = *(const float2*)&w1[co * 64 + cp * 2];
        uint32_t off = (uint32_t)(co * 128 + cp * 4);
        *(__half2*)(wb8 + swz128(off)) = __floats2half2_rn(wv.x, wv.y);
    }
    if (tid < C) b1s[tid] = b1[tid];
    __syncthreads();

    uint32_t xs_base = smem_u32(Xs);
    uint32_t ws_base = smem_u32(W1s);
    int li = lane >> 3, lr = lane & 7;

    float acc[8][4];
    #pragma unroll
    for (int ni = 0; ni < 8; ++ni)
        #pragma unroll
        for (int d = 0; d < 4; ++d) acc[ni][d] = 0.f;

    #pragma unroll
    for (int ki = 0; ki < 4; ++ki) {
        uint32_t a[4];
        {
            uint32_t off = (uint32_t)((wid * 16 + (li & 1) * 8 + lr) * 128
                                      + (li >> 1) * 16 + ki * 32);
            LDSM_X4(a[0], a[1], a[2], a[3], xs_base + swz128(off));
        }
        uint32_t bf[8][2];
        #pragma unroll
        for (int ci = 0; ci < 4; ++ci) {
            uint32_t off = (uint32_t)((ci * 16 + (li & 1) * 8 + lr) * 128
                                      + (li >> 1) * 16 + ki * 32);
            uint32_t t0, t1, t2, t3;
            LDSM_X4(t0, t1, t2, t3, ws_base + swz128(off));
            bf[ci * 2 + 0][0] = t0; bf[ci * 2 + 0][1] = t2;
            bf[ci * 2 + 1][0] = t1; bf[ci * 2 + 1][1] = t3;
        }
        #pragma unroll
        for (int ni = 0; ni < 8; ++ni)
            MMA16816(acc[ni], a, bf[ni]);
    }

    #pragma unroll
    for (int ni = 0; ni < 8; ++ni) {
        int c = ni * 8 + (lane & 3) * 2;
        float bv0 = b1s[c], bv1 = b1s[c + 1];
        #pragma unroll
        for (int h = 0; h < 2; ++h) {
            int px = wid * 16 + h * 8 + (lane >> 2);
            *(__half2*)&Os[px * 72 + c] =
                __floats2half2_rn(acc[ni][h * 2 + 0] + bv0,
                                  acc[ni][h * 2 + 1] + bv1);
        }
    }
    __syncthreads();

    char* ob8 = (char*)Os;
    for (int idx = tid; idx < 512; idx += 128) {
        int px = idx >> 3, seg = idx & 7;
        uint4 v = *(uint4*)(ob8 + px * 144 + seg * 16);
        *(uint4*)&g_tokensH[((size_t)(b * HW + px0 + px)) * C + seg * 8] = v;
    }
}

// ---------------------------------------------------------------------------
// Stage 3: grid + bilinear gather (fp16 tokens) -> V rows [n][k] fp16.
// ---------------------------------------------------------------------------
__global__ void gather_kernel() {
    __shared__ float sv[8 * 1032];
    int n0 = blockIdx.x * 8;
    int tid = threadIdx.x;
    int slot = tid >> 1, half = tid & 1;
    int pl = slot >> 4, pix = slot & 15;
    int n = n0 + pl;
    int b = n / NPB; int r = n - b * NPB;
    int i = r / PW;  int j = r - i * PW;

    float offx = g_params[n * 4 + 0];
    float offy = g_params[n * 4 + 1];
    float scx  = g_params[n * 4 + 2];
    float scy  = g_params[n * 4 + 3];

    int py = pix >> 2, px = pix & 3;
    const float inv223 = 1.0f / 223.0f;
    float gx = (-1.0f + 2.0f * (4 * j + 1.5f) * inv223)
             + ((px - 1.5f) * 2.0f * inv223) * (1.0f + scx) + offx;
    float gy = (-1.0f + 2.0f * (4 * i + 1.5f) * inv223)
             + ((py - 1.5f) * 2.0f * inv223) * (1.0f + scy) + offy;
    float ix = (gx + 1.0f) * 0.5f * 223.0f;
    float iy = (gy + 1.0f) * 0.5f * 223.0f;

    float x0f = floorf(ix), y0f = floorf(iy);
    int x0 = (int)x0f, y0 = (int)y0f;
    float wx1 = ix - x0f, wx0 = 1.f - wx1;
    float wy1 = iy - y0f, wy0 = 1.f - wy1;

    float acc[32];
    #pragma unroll
    for (int q = 0; q < 32; ++q) acc[q] = 0.f;

    const __half* tb = g_tokensH + ((size_t)b * HW) * C + half * 32;
    int   xs[4] = { x0, x0 + 1, x0,     x0 + 1 };
    int   ys[4] = { y0, y0,     y0 + 1, y0 + 1 };
    float ws[4] = { wx0 * wy0, wx1 * wy0, wx0 * wy1, wx1 * wy1 };

    #pragma unroll
    for (int cr = 0; cr < 4; ++cr) {
        int xc = xs[cr], yc = ys[cr];
        if ((unsigned)xc < (unsigned)W && (unsigned)yc < (unsigned)H) {
            float wgt = ws[cr];
            const uint4* p4 = (const uint4*)(tb + ((size_t)yc * W + xc) * C);
            #pragma unroll
            for (int q = 0; q < 4; ++q) {        // 4 x 16B = 32 halfs
                uint4 t = p4[q];
                uint32_t wd[4] = { t.x, t.y, t.z, t.w };
                #pragma unroll
                for (int s = 0; s < 4; ++s) {
                    float2 f = __half22float2(*(__half2*)&wd[s]);
                    acc[q * 8 + s * 2 + 0] += wgt * f.x;
                    acc[q * 8 + s * 2 + 1] += wgt * f.y;
                }
            }
        }
    }

    #pragma unroll
    for (int q = 0; q < 32; ++q) {
        int c = half * 32 + q;
        sv[pl * 1032 + c * 16 + pix] = acc[q];   // k = c*16 + py*4 + px
    }
    __syncthreads();

    for (int idx = tid; idx < 8 * 512; idx += 256) {
        int plw = idx >> 9, kk = (idx & 511) * 2;
        float v0 = sv[plw * 1032 + kk];
        float v1 = sv[plw * 1032 + kk + 1];
        *(__half2*)&g_Vf[(size_t)(n0 + plw) * KDIM + kk] = __floats2half2_rn(v0, v1);
    }
}

// ---------------------------------------------------------------------------
// Stage 4: fp16 mma.sync GEMM  out(768 x 25088) = W2(768x1024)*V + b2
// R11/R14 config (BK=64, tile 128x128, warp 64x32, 3-stage, one barrier per
// chunk, prefetch at top, 256 thr, occ 2) + BRANCH-BASED ks stagger:
// even warps run ks 0,1,2,3; odd warps 2,3,0,1 (all offsets compile-time).
// ---------------------------------------------------------------------------
#define BK 64
#define NCHUNK (KDIM / BK)          // 16
#define ROWB 144                    // 128B data + 16B pad per row
#define BUFB (128 * ROWB)           // 18432 B per operand buffer
#define STAGEB (2 * BUFB)           // A, B
#define NSTG 3
#define GEMM_SMEM (NSTG * STAGEB)   // 110592 B

__device__ __forceinline__ void load_chunk(uint32_t stage, int m0, int n0,
                                           int kc, int tid) {
    #pragma unroll
    for (int it = 0; it < 4; ++it) {
        int idx = tid + it * 256;               // 0..1023
        int row = idx >> 3, seg = idx & 7;
        uint32_t dst = (uint32_t)(row * ROWB + seg * 16);
        size_t ea = (((size_t)(m0 + row)) << 11) + (size_t)kc * 128 + seg * 16; // bytes
        size_t eb = (((size_t)(n0 + row)) << 11) + (size_t)kc * 128 + seg * 16;
        CP_ASYNC16(stage + dst,        (const char*)g_W2f + ea);
        CP_ASYNC16(stage + BUFB + dst, (const char*)g_Vf  + eb);
    }
}

// one k-step (16 k-elems, compile-time KS): 6 LDSM.x4 + 16 MMA
#define DO_KS(KS) do {                                                        \
    const uint32_t koff = (uint32_t)((KS) * 32);                              \
    uint32_t ah[4][4], bh[4][2];                                              \
    _Pragma("unroll")                                                         \
    for (int mi = 0; mi < 4; ++mi) {                                          \
        uint32_t ad = stg + a_off + koff + (uint32_t)(mi * 16 * ROWB);        \
        LDSM_X4(ah[mi][0], ah[mi][1], ah[mi][2], ah[mi][3], ad);              \
    }                                                                         \
    _Pragma("unroll")                                                         \
    for (int nh = 0; nh < 2; ++nh) {                                          \
        uint32_t bd = stg + BUFB + b_off + koff + (uint32_t)(nh * 16 * ROWB); \
        uint32_t t0, t1, t2, t3;                                              \
        LDSM_X4(t0, t1, t2, t3, bd);                                          \
        bh[nh * 2 + 0][0] = t0; bh[nh * 2 + 0][1] = t2;                       \
        bh[nh * 2 + 1][0] = t1; bh[nh * 2 + 1][1] = t3;                       \
    }                                                                         \
    _Pragma("unroll")                                                         \
    for (int mi = 0; mi < 4; ++mi)                                            \
        _Pragma("unroll")                                                     \
        for (int ni = 0; ni < 4; ++ni)                                        \
            MMA16816(acc[mi][ni], ah[mi], bh[ni]);                            \
} while (0)

__global__ void __launch_bounds__(256, 2) gemm_kernel(const float* __restrict__ b2,
                                                      float* __restrict__ out) {
    extern __shared__ char smem[];
    uint32_t sbase = smem_u32(smem);
    int tid = threadIdx.x;
    int wid = tid >> 5, lane = tid & 31;
    int m0 = blockIdx.x * 128;        // 6 m-tiles fastest (B-tile reuse in L2)
    int n0 = blockIdx.y * 128;        // 196 n-tiles
    int wm = (wid & 1) * 64;
    int wn = (wid >> 1) * 32;

    float acc[4][4][4];
    #pragma unroll
    for (int a = 0; a < 4; ++a)
        #pragma unroll
        for (int b = 0; b < 4; ++b)
            #pragma unroll
            for (int d = 0; d < 4; ++d) acc[a][b][d] = 0.f;

    int li = lane >> 3, lr = lane & 7;
    uint32_t a_off = (uint32_t)((wm + (li & 1) * 8 + lr) * ROWB + (li >> 1) * 16);
    uint32_t b_off = (uint32_t)((wn + (li & 1) * 8 + lr) * ROWB + (li >> 1) * 16);
    bool even_warp = (wid & 1) == 0;

    // prologue: chunks 0,1
    load_chunk(sbase + 0 * STAGEB, m0, n0, 0, tid); CP_COMMIT();
    load_chunk(sbase + 1 * STAGEB, m0, n0, 1, tid); CP_COMMIT();

    for (int kt = 0; kt < NCHUNK; ++kt) {
        if (kt < NCHUNK - 1) { CP_WAIT(1); } else { CP_WAIT(0); }
        __syncthreads();                 // single barrier per chunk

        // prefetch chunk kt+2 (measured-best position: right after barrier)
        int c = kt + 2;
        if (c < NCHUNK) {
            load_chunk(sbase + (uint32_t)(c % NSTG) * STAGEB, m0, n0, c, tid);
            CP_COMMIT();
        }

        uint32_t stg = sbase + (uint32_t)(kt % NSTG) * STAGEB;
        if (even_warp) {
            DO_KS(0); DO_KS(1); DO_KS(2); DO_KS(3);
        } else {
            DO_KS(2); DO_KS(3); DO_KS(0); DO_KS(1);
        }
    }

    // epilogue
    #pragma unroll
    for (int mi = 0; mi < 4; ++mi) {
        #pragma unroll
        for (int hrow = 0; hrow < 2; ++hrow) {
            int m = m0 + wm + mi * 16 + hrow * 8 + (lane >> 2);
            float bias = b2[m];
            #pragma unroll
            for (int ni = 0; ni < 4; ++ni) {
                int n = n0 + wn + ni * 8 + (lane & 3) * 2;
                int bb = n / NPB;
                int rr = n - bb * NPB;
                float2 v;
                v.x = acc[mi][ni][hrow * 2 + 0] + bias;
                v.y = acc[mi][ni][hrow * 2 + 1] + bias;
                *(float2*)&out[(size_t)bb * (E * NPB) + (size_t)m * NPB + rr] = v;
            }
        }
    }
}

// ---------------------------------------------------------------------------
extern "C" void kernel_launch(void* const* d_in, const int* in_sizes, int n_in,
                              void* d_out, int out_size) {
    const float* x     = (const float*)d_in[0];
    const float* w1    = (const float*)d_in[1];
    const float* b1    = (const float*)d_in[2];
    const float* w2    = (const float*)d_in[3];
    const float* b2    = (const float*)d_in[4];
    const float* w_off = (const float*)d_in[5];
    const float* b_off = (const float*)d_in[6];
    const float* w_sc  = (const float*)d_in[7];
    const float* b_sc  = (const float*)d_in[8];
    float* out = (float*)d_out;

    cudaFuncSetAttribute(gemm_kernel, cudaFuncAttributeMaxDynamicSharedMemorySize,
                         GEMM_SMEM);

    params_kernel<<<dim3(PH, BATCH), 256>>>(x, w_off, b_off, w_sc, b_sc, w2);
    tokens_kernel<<<dim3(HW / 64, BATCH), 128>>>(x, w1, b1);
    gather_kernel<<<NP / 8, 256>>>();
    gemm_kernel<<<dim3(E / 128, NP / 128), 256, GEMM_SMEM>>>(b2, out);
}

// round 16
// speedup vs baseline: 1.0427x; 1.0427x over previous
#include <cuda_runtime.h>
#include <cuda_fp16.h>
#include <cstdint>

#define BATCH 8
#define C 64
#define H 224
#define W 224
#define E 768
#define PH 56
#define PW 56
#define HW (H*W)        // 50176
#define NPB (PH*PW)     // 3136 patches per batch
#define NP (BATCH*NPB)  // 25088 total patches
#define KDIM 1024       // C * 4 * 4

// ---------------- scratch (device globals: allocation-free) ----------------
__device__ __half g_tokensH[BATCH * HW * C];        // NHWC fp16 [b][h][w][c]
__device__ __half g_Vf[(size_t)NP * KDIM];          // [n][k] fp16
__device__ __half g_W2f[E * KDIM];                  // [m][k] fp16
__device__ float  g_pool[NP * C];                   // per-patch per-ch sums
__device__ float  g_params[NP * 4];                 // offx, offy, scx, scy

// ======================= PTX helpers (sm_100 base ISA only) ================
__device__ __forceinline__ uint32_t smem_u32(const void* p) {
    uint32_t a;
    asm("{ .reg .u64 t; cvta.to.shared.u64 t, %1; cvt.u32.u64 %0, t; }" : "=r"(a) : "l"(p));
    return a;
}
#define CP_ASYNC16(dst, src) \
    asm volatile("cp.async.cg.shared.global [%0], [%1], 16;" :: "r"(dst), "l"(src) : "memory")
#define CP_COMMIT() asm volatile("cp.async.commit_group;" ::: "memory")
#define CP_WAIT(n)  asm volatile("cp.async.wait_group %0;" :: "n"(n) : "memory")

#define LDSM_X4(r0, r1, r2, r3, addr) \
    asm volatile("ldmatrix.sync.aligned.m8n8.x4.shared.b16 {%0,%1,%2,%3}, [%4];" \
        : "=r"(r0), "=r"(r1), "=r"(r2), "=r"(r3) : "r"(addr))

#define MMA16816(d, a, b) \
    asm volatile("mma.sync.aligned.m16n8k16.row.col.f32.f16.f16.f32 " \
        "{%0,%1,%2,%3}, {%4,%5,%6,%7}, {%8,%9}, {%0,%1,%2,%3};" \
        : "+f"((d)[0]), "+f"((d)[1]), "+f"((d)[2]), "+f"((d)[3]) \
        : "r"((a)[0]), "r"((a)[1]), "r"((a)[2]), "r"((a)[3]), \
          "r"((b)[0]), "r"((b)[1]))

__device__ __forceinline__ uint32_t swz128(uint32_t off) {
    return off ^ ((off >> 3) & 0x70);
}

// ---------------------------------------------------------------------------
// Stage 1: tokens (1x1 conv, fp16 mma) + per-patch pool sums, ONE x pass.
// Block = 4 rows x 16 cols (patch-aligned: 4 whole patches), 128 thr, 4 warps.
// px = row*16 + wc. MMA math identical to before (px is just a row index).
// ---------------------------------------------------------------------------
__global__ void __launch_bounds__(128) tokens_kernel(const float* __restrict__ x,
                                                     const float* __restrict__ w1,
                                                     const float* __restrict__ b1) {
    __shared__ __half Xs[64 * 64];   // [px][k], 128B rows, swizzled
    __shared__ __half W1s[64 * 64];  // [c][k],  128B rows, swizzled
    __shared__ __half Os[64 * 72];   // [px][c], pad-72 rows (conflict-free)
    __shared__ float b1s[C];

    int b  = blockIdx.z;
    int i  = blockIdx.y;             // patch row band 0..55
    int w0 = blockIdx.x * 16;        // 14 col tiles
    int h0 = i * 4;
    int tid = threadIdx.x;
    int wid = tid >> 5, lane = tid & 31;

    char* xb8 = (char*)Xs;
    char* wb8 = (char*)W1s;

    // stage X: x[b][k][h0+row][w0+wc] -> Xs[px][k] fp16 swizzled
    const float* xb = x + ((size_t)b * C) * HW + (size_t)h0 * W + w0;
    for (int idx = tid; idx < 64 * 32; idx += 128) {
        int px = idx & 63, kp = idx >> 6;        // kp = channel pair
        int row = px >> 4, wc = px & 15;
        size_t o = (size_t)(2 * kp) * HW + row * W + wc;
        float v0 = xb[o];
        float v1 = xb[o + HW];
        uint32_t off = (uint32_t)(px * 128 + kp * 4);
        *(__half2*)(xb8 + swz128(off)) = __floats2half2_rn(v0, v1);
    }
    for (int idx = tid; idx < 64 * 32; idx += 128) {
        int co = idx >> 5, cp = idx & 31;
        float2 wv = *(const float2*)&w1[co * 64 + cp * 2];
        uint32_t off = (uint32_t)(co * 128 + cp * 4);
        *(__half2*)(wb8 + swz128(off)) = __floats2half2_rn(wv.x, wv.y);
    }
    if (tid < C) b1s[tid] = b1[tid];
    __syncthreads();

    // pool sums: thread = (patch p 0..3, channel pair cpair 0..31)
    {
        int p = tid >> 5, cpair = tid & 31;
        float s0 = 0.f, s1 = 0.f;
        #pragma unroll
        for (int u = 0; u < 16; ++u) {
            int px = (u >> 2) * 16 + p * 4 + (u & 3);   // row*16 + col
            uint32_t off = (uint32_t)(px * 128 + cpair * 4);
            __half2 hv = *(__half2*)(xb8 + swz128(off));
            float2 f = __half22float2(hv);
            s0 += f.x; s1 += f.y;
        }
        int n = b * NPB + i * PW + (w0 >> 2) + p;
        *(float2*)&g_pool[n * C + cpair * 2] = make_float2(s0, s1);
    }

    uint32_t xs_base = smem_u32(Xs);
    uint32_t ws_base = smem_u32(W1s);
    int li = lane >> 3, lr = lane & 7;

    float acc[8][4];
    #pragma unroll
    for (int ni = 0; ni < 8; ++ni)
        #pragma unroll
        for (int d = 0; d < 4; ++d) acc[ni][d] = 0.f;

    #pragma unroll
    for (int ki = 0; ki < 4; ++ki) {
        uint32_t a[4];
        {
            uint32_t off = (uint32_t)((wid * 16 + (li & 1) * 8 + lr) * 128
                                      + (li >> 1) * 16 + ki * 32);
            LDSM_X4(a[0], a[1], a[2], a[3], xs_base + swz128(off));
        }
        uint32_t bf[8][2];
        #pragma unroll
        for (int ci = 0; ci < 4; ++ci) {
            uint32_t off = (uint32_t)((ci * 16 + (li & 1) * 8 + lr) * 128
                                      + (li >> 1) * 16 + ki * 32);
            uint32_t t0, t1, t2, t3;
            LDSM_X4(t0, t1, t2, t3, ws_base + swz128(off));
            bf[ci * 2 + 0][0] = t0; bf[ci * 2 + 0][1] = t2;
            bf[ci * 2 + 1][0] = t1; bf[ci * 2 + 1][1] = t3;
        }
        #pragma unroll
        for (int ni = 0; ni < 8; ++ni)
            MMA16816(acc[ni], a, bf[ni]);
    }

    #pragma unroll
    for (int ni = 0; ni < 8; ++ni) {
        int c = ni * 8 + (lane & 3) * 2;
        float bv0 = b1s[c], bv1 = b1s[c + 1];
        #pragma unroll
        for (int h = 0; h < 2; ++h) {
            int px = wid * 16 + h * 8 + (lane >> 2);
            *(__half2*)&Os[px * 72 + c] =
                __floats2half2_rn(acc[ni][h * 2 + 0] + bv0,
                                  acc[ni][h * 2 + 1] + bv1);
        }
    }
    __syncthreads();

    // NHWC write: pixel (h0+row, w0+wc), 128B per pixel
    char* ob8 = (char*)Os;
    for (int idx = tid; idx < 512; idx += 128) {
        int px = idx >> 3, seg = idx & 7;
        int h = h0 + (px >> 4), w = w0 + (px & 15);
        uint4 v = *(uint4*)(ob8 + px * 144 + seg * 16);
        *(uint4*)&g_tokensH[((size_t)(b * HW + h * W + w)) * C + seg * 8] = v;
    }
}

// ---------------------------------------------------------------------------
// Stage 2: params from pooled sums (6.4MB read) + w2->fp16 conversion.
// Block 256 thr = 8 warps; warp = 1 patch; lane = channel pair.
// ---------------------------------------------------------------------------
__global__ void params_kernel(const float* __restrict__ w_off,
                              const float* __restrict__ b_off,
                              const float* __restrict__ w_sc,
                              const float* __restrict__ b_sc,
                              const float* __restrict__ w2) {
    __shared__ float wofs[2 * C], wscs[2 * C];
    int tid = threadIdx.x;

    // folded wsplit: convert w2 to fp16 (grid-strided)
    {
        int gtid = blockIdx.x * 256 + tid;
        int nthreads = gridDim.x * 256;
        for (int idx = gtid; idx < E * KDIM / 2; idx += nthreads) {
            float2 v = ((const float2*)w2)[idx];
            ((__half2*)g_W2f)[idx] = __floats2half2_rn(v.x, v.y);
        }
    }

    if (tid < 2 * C) {
        wofs[tid] = w_off[tid];
        wscs[tid] = w_sc[tid];
    }
    __syncthreads();

    int warp = tid >> 5, lane = tid & 31;
    int n = blockIdx.x * 8 + warp;
    int c0 = lane * 2;

    float2 pv = *(const float2*)&g_pool[n * C + c0];
    float g0 = pv.x * (1.0f / 16.0f);
    float g1 = pv.y * (1.0f / 16.0f);
    g0 = (g0 > 0.f) ? g0 : 0.01f * g0;
    g1 = (g1 > 0.f) ? g1 : 0.01f * g1;

    float aox = g0 * wofs[c0]     + g1 * wofs[c0 + 1];
    float aoy = g0 * wofs[C + c0] + g1 * wofs[C + c0 + 1];
    float asx = g0 * wscs[c0]     + g1 * wscs[c0 + 1];
    float asy = g0 * wscs[C + c0] + g1 * wscs[C + c0 + 1];

    #pragma unroll
    for (int s = 16; s >= 1; s >>= 1) {
        aox += __shfl_xor_sync(0xffffffffu, aox, s);
        aoy += __shfl_xor_sync(0xffffffffu, aoy, s);
        asx += __shfl_xor_sync(0xffffffffu, asx, s);
        asy += __shfl_xor_sync(0xffffffffu, asy, s);
    }
    if (lane == 0) {
        g_params[n * 4 + 0] = (aox + b_off[0]) * (1.0f / 56.0f);
        g_params[n * 4 + 1] = (aoy + b_off[1]) * (1.0f / 56.0f);
        g_params[n * 4 + 2] = asx + b_sc[0];
        g_params[n * 4 + 3] = asy + b_sc[1];
    }
}

// ---------------------------------------------------------------------------
// Stage 3: grid + bilinear gather (fp16 tokens) -> V rows [n][k] fp16.
// ---------------------------------------------------------------------------
__global__ void gather_kernel() {
    __shared__ float sv[8 * 1032];
    int n0 = blockIdx.x * 8;
    int tid = threadIdx.x;
    int slot = tid >> 1, half = tid & 1;
    int pl = slot >> 4, pix = slot & 15;
    int n = n0 + pl;
    int b = n / NPB; int r = n - b * NPB;
    int i = r / PW;  int j = r - i * PW;

    float offx = g_params[n * 4 + 0];
    float offy = g_params[n * 4 + 1];
    float scx  = g_params[n * 4 + 2];
    float scy  = g_params[n * 4 + 3];

    int py = pix >> 2, px = pix & 3;
    const float inv223 = 1.0f / 223.0f;
    float gx = (-1.0f + 2.0f * (4 * j + 1.5f) * inv223)
             + ((px - 1.5f) * 2.0f * inv223) * (1.0f + scx) + offx;
    float gy = (-1.0f + 2.0f * (4 * i + 1.5f) * inv223)
             + ((py - 1.5f) * 2.0f * inv223) * (1.0f + scy) + offy;
    float ix = (gx + 1.0f) * 0.5f * 223.0f;
    float iy = (gy + 1.0f) * 0.5f * 223.0f;

    float x0f = floorf(ix), y0f = floorf(iy);
    int x0 = (int)x0f, y0 = (int)y0f;
    float wx1 = ix - x0f, wx0 = 1.f - wx1;
    float wy1 = iy - y0f, wy0 = 1.f - wy1;

    float acc[32];
    #pragma unroll
    for (int q = 0; q < 32; ++q) acc[q] = 0.f;

    const __half* tb = g_tokensH + ((size_t)b * HW) * C + half * 32;
    int   xs[4] = { x0, x0 + 1, x0,     x0 + 1 };
    int   ys[4] = { y0, y0,     y0 + 1, y0 + 1 };
    float ws[4] = { wx0 * wy0, wx1 * wy0, wx0 * wy1, wx1 * wy1 };

    #pragma unroll
    for (int cr = 0; cr < 4; ++cr) {
        int xc = xs[cr], yc = ys[cr];
        if ((unsigned)xc < (unsigned)W && (unsigned)yc < (unsigned)H) {
            float wgt = ws[cr];
            const uint4* p4 = (const uint4*)(tb + ((size_t)yc * W + xc) * C);
            #pragma unroll
            for (int q = 0; q < 4; ++q) {        // 4 x 16B = 32 halfs
                uint4 t = p4[q];
                uint32_t wd[4] = { t.x, t.y, t.z, t.w };
                #pragma unroll
                for (int s = 0; s < 4; ++s) {
                    float2 f = __half22float2(*(__half2*)&wd[s]);
                    acc[q * 8 + s * 2 + 0] += wgt * f.x;
                    acc[q * 8 + s * 2 + 1] += wgt * f.y;
                }
            }
        }
    }

    #pragma unroll
    for (int q = 0; q < 32; ++q) {
        int c = half * 32 + q;
        sv[pl * 1032 + c * 16 + pix] = acc[q];   // k = c*16 + py*4 + px
    }
    __syncthreads();

    for (int idx = tid; idx < 8 * 512; idx += 256) {
        int plw = idx >> 9, kk = (idx & 511) * 2;
        float v0 = sv[plw * 1032 + kk];
        float v1 = sv[plw * 1032 + kk + 1];
        *(__half2*)&g_Vf[(size_t)(n0 + plw) * KDIM + kk] = __floats2half2_rn(v0, v1);
    }
}

// ---------------------------------------------------------------------------
// Stage 4: fp16 mma.sync GEMM  out(768 x 25088) = W2(768x1024)*V + b2
// EXACT R14 measured-best config: BK=64, tile 128x128, warp 64x32, 3-stage
// cp.async, one barrier per chunk, prefetch-before-compute, 256 thr, occ 2.
// ---------------------------------------------------------------------------
#define BK 64
#define NCHUNK (KDIM / BK)          // 16
#define ROWB 144                    // 128B data + 16B pad per row
#define BUFB (128 * ROWB)           // 18432 B per operand buffer
#define STAGEB (2 * BUFB)           // A, B
#define NSTG 3
#define GEMM_SMEM (NSTG * STAGEB)   // 110592 B

__device__ __forceinline__ void load_chunk(uint32_t stage, int m0, int n0,
                                           int kc, int tid) {
    #pragma unroll
    for (int it = 0; it < 4; ++it) {
        int idx = tid + it * 256;               // 0..1023
        int row = idx >> 3, seg = idx & 7;
        uint32_t dst = (uint32_t)(row * ROWB + seg * 16);
        size_t ea = (((size_t)(m0 + row)) << 11) + (size_t)kc * 128 + seg * 16; // bytes
        size_t eb = (((size_t)(n0 + row)) << 11) + (size_t)kc * 128 + seg * 16;
        CP_ASYNC16(stage + dst,        (const char*)g_W2f + ea);
        CP_ASYNC16(stage + BUFB + dst, (const char*)g_Vf  + eb);
    }
}

__global__ void __launch_bounds__(256, 2) gemm_kernel(const float* __restrict__ b2,
                                                      float* __restrict__ out) {
    extern __shared__ char smem[];
    uint32_t sbase = smem_u32(smem);
    int tid = threadIdx.x;
    int wid = tid >> 5, lane = tid & 31;
    int m0 = blockIdx.x * 128;        // 6 m-tiles fastest (B-tile reuse in L2)
    int n0 = blockIdx.y * 128;        // 196 n-tiles
    int wm = (wid & 1) * 64;
    int wn = (wid >> 1) * 32;

    float acc[4][4][4];
    #pragma unroll
    for (int a = 0; a < 4; ++a)
        #pragma unroll
        for (int b = 0; b < 4; ++b)
            #pragma unroll
            for (int d = 0; d < 4; ++d) acc[a][b][d] = 0.f;

    int li = lane >> 3, lr = lane & 7;
    uint32_t a_off = (uint32_t)((wm + (li & 1) * 8 + lr) * ROWB + (li >> 1) * 16);
    uint32_t b_off = (uint32_t)((wn + (li & 1) * 8 + lr) * ROWB + (li >> 1) * 16);

    // prologue: chunks 0,1
    load_chunk(sbase + 0 * STAGEB, m0, n0, 0, tid); CP_COMMIT();
    load_chunk(sbase + 1 * STAGEB, m0, n0, 1, tid); CP_COMMIT();

    for (int kt = 0; kt < NCHUNK; ++kt) {
        if (kt < NCHUNK - 1) { CP_WAIT(1); } else { CP_WAIT(0); }
        __syncthreads();                 // single barrier per chunk

        // prefetch chunk kt+2 into stage (kt+2)%3 (read finished at iter kt-1)
        int c = kt + 2;
        if (c < NCHUNK) {
            load_chunk(sbase + (uint32_t)(c % NSTG) * STAGEB, m0, n0, c, tid);
            CP_COMMIT();
        }

        uint32_t stg = sbase + (uint32_t)(kt % NSTG) * STAGEB;
        #pragma unroll
        for (int ks = 0; ks < 4; ++ks) {
            uint32_t koff = (uint32_t)(ks * 32);   // 16 k-elems = 32 bytes
            uint32_t ah[4][4], bh[4][2];
            #pragma unroll
            for (int mi = 0; mi < 4; ++mi) {
                uint32_t ad = stg + a_off + koff + (uint32_t)(mi * 16 * ROWB);
                LDSM_X4(ah[mi][0], ah[mi][1], ah[mi][2], ah[mi][3], ad);
            }
            #pragma unroll
            for (int nh = 0; nh < 2; ++nh) {
                uint32_t bd = stg + BUFB + b_off + koff + (uint32_t)(nh * 16 * ROWB);
                uint32_t t0, t1, t2, t3;
                LDSM_X4(t0, t1, t2, t3, bd);
                bh[nh * 2 + 0][0] = t0; bh[nh * 2 + 0][1] = t2;
                bh[nh * 2 + 1][0] = t1; bh[nh * 2 + 1][1] = t3;
            }
            #pragma unroll
            for (int mi = 0; mi < 4; ++mi)
                #pragma unroll
                for (int ni = 0; ni < 4; ++ni)
                    MMA16816(acc[mi][ni], ah[mi], bh[ni]);
        }
    }

    // epilogue
    #pragma unroll
    for (int mi = 0; mi < 4; ++mi) {
        #pragma unroll
        for (int hrow = 0; hrow < 2; ++hrow) {
            int m = m0 + wm + mi * 16 + hrow * 8 + (lane >> 2);
            float bias = b2[m];
            #pragma unroll
            for (int ni = 0; ni < 4; ++ni) {
                int n = n0 + wn + ni * 8 + (lane & 3) * 2;
                int bb = n / NPB;
                int rr = n - bb * NPB;
                float2 v;
                v.x = acc[mi][ni][hrow * 2 + 0] + bias;
                v.y = acc[mi][ni][hrow * 2 + 1] + bias;
                *(float2*)&out[(size_t)bb * (E * NPB) + (size_t)m * NPB + rr] = v;
            }
        }
    }
}

// ---------------------------------------------------------------------------
extern "C" void kernel_launch(void* const* d_in, const int* in_sizes, int n_in,
                              void* d_out, int out_size) {
    const float* x     = (const float*)d_in[0];
    const float* w1    = (const float*)d_in[1];
    const float* b1    = (const float*)d_in[2];
    const float* w2    = (const float*)d_in[3];
    const float* b2    = (const float*)d_in[4];
    const float* w_off = (const float*)d_in[5];
    const float* b_off = (const float*)d_in[6];
    const float* w_sc  = (const float*)d_in[7];
    const float* b_sc  = (const float*)d_in[8];
    float* out = (float*)d_out;

    cudaFuncSetAttribute(gemm_kernel, cudaFuncAttributeMaxDynamicSharedMemorySize,
                         GEMM_SMEM);

    // tokens(+pool) -> params(from pool, +w2 convert) -> gather -> gemm
    tokens_kernel<<<dim3(W / 16, PH, BATCH), 128>>>(x, w1, b1);
    params_kernel<<<NP / 8, 256>>>(w_off, b_off, w_sc, b_sc, w2);
    gather_kernel<<<NP / 8, 256>>>();
    gemm_kernel<<<dim3(E / 128, NP / 128), 256, GEMM_SMEM>>>(b2, out);
}

// round 17
// speedup vs baseline: 1.0576x; 1.0143x over previous
#include <cuda_runtime.h>
#include <cuda_fp16.h>
#include <cstdint>

#define BATCH 8
#define C 64
#define H 224
#define W 224
#define E 768
#define PH 56
#define PW 56
#define HW (H*W)        // 50176
#define NPB (PH*PW)     // 3136 patches per batch
#define NP (BATCH*NPB)  // 25088 total patches
#define KDIM 1024       // C * 4 * 4

// NOTE: k-dimension of the big GEMM uses PERMUTED index k' = pix*64 + c
// (applied identically to W2f and Vf; GEMM result is invariant).

// ---------------- scratch (device globals: allocation-free) ----------------
__device__ __half g_tokensH[BATCH * HW * C];        // NHWC fp16 [b][h][w][c]
__device__ __half g_Vf[(size_t)NP * KDIM];          // [n][k'] fp16
__device__ __half g_W2f[E * KDIM];                  // [m][k'] fp16
__device__ float  g_pool[NP * C];                   // per-patch per-ch sums
__device__ float  g_params[NP * 4];                 // offx, offy, scx, scy

// ======================= PTX helpers (sm_100 base ISA only) ================
__device__ __forceinline__ uint32_t smem_u32(const void* p) {
    uint32_t a;
    asm("{ .reg .u64 t; cvta.to.shared.u64 t, %1; cvt.u32.u64 %0, t; }" : "=r"(a) : "l"(p));
    return a;
}
#define CP_ASYNC16(dst, src) \
    asm volatile("cp.async.cg.shared.global [%0], [%1], 16;" :: "r"(dst), "l"(src) : "memory")
#define CP_COMMIT() asm volatile("cp.async.commit_group;" ::: "memory")
#define CP_WAIT(n)  asm volatile("cp.async.wait_group %0;" :: "n"(n) : "memory")

#define LDSM_X4(r0, r1, r2, r3, addr) \
    asm volatile("ldmatrix.sync.aligned.m8n8.x4.shared.b16 {%0,%1,%2,%3}, [%4];" \
        : "=r"(r0), "=r"(r1), "=r"(r2), "=r"(r3) : "r"(addr))

#define MMA16816(d, a, b) \
    asm volatile("mma.sync.aligned.m16n8k16.row.col.f32.f16.f16.f32 " \
        "{%0,%1,%2,%3}, {%4,%5,%6,%7}, {%8,%9}, {%0,%1,%2,%3};" \
        : "+f"((d)[0]), "+f"((d)[1]), "+f"((d)[2]), "+f"((d)[3]) \
        : "r"((a)[0]), "r"((a)[1]), "r"((a)[2]), "r"((a)[3]), \
          "r"((b)[0]), "r"((b)[1]))

__device__ __forceinline__ uint32_t swz128(uint32_t off) {
    return off ^ ((off >> 3) & 0x70);
}

// ---------------------------------------------------------------------------
// Stage 1: tokens (1x1 conv, fp16 mma) + per-patch pool sums, ONE x pass.
// Block = 4 rows x 16 cols (4 whole patches), 128 thr, 4 warps.
// ---------------------------------------------------------------------------
__global__ void __launch_bounds__(128) tokens_kernel(const float* __restrict__ x,
                                                     const float* __restrict__ w1,
                                                     const float* __restrict__ b1) {
    __shared__ __half Xs[64 * 64];   // [px][k], 128B rows, swizzled
    __shared__ __half W1s[64 * 64];  // [c][k],  128B rows, swizzled
    __shared__ __half Os[64 * 72];   // [px][c], pad-72 rows (conflict-free)
    __shared__ float b1s[C];

    int b  = blockIdx.z;
    int i  = blockIdx.y;             // patch row band 0..55
    int w0 = blockIdx.x * 16;        // 14 col tiles
    int h0 = i * 4;
    int tid = threadIdx.x;
    int wid = tid >> 5, lane = tid & 31;

    char* xb8 = (char*)Xs;
    char* wb8 = (char*)W1s;

    const float* xb = x + ((size_t)b * C) * HW + (size_t)h0 * W + w0;
    for (int idx = tid; idx < 64 * 32; idx += 128) {
        int px = idx & 63, kp = idx >> 6;        // kp = channel pair
        int row = px >> 4, wc = px & 15;
        size_t o = (size_t)(2 * kp) * HW + row * W + wc;
        float v0 = xb[o];
        float v1 = xb[o + HW];
        uint32_t off = (uint32_t)(px * 128 + kp * 4);
        *(__half2*)(xb8 + swz128(off)) = __floats2half2_rn(v0, v1);
    }
    for (int idx = tid; idx < 64 * 32; idx += 128) {
        int co = idx >> 5, cp = idx & 31;
        float2 wv = *(const float2*)&w1[co * 64 + cp * 2];
        uint32_t off = (uint32_t)(co * 128 + cp * 4);
        *(__half2*)(wb8 + swz128(off)) = __floats2half2_rn(wv.x, wv.y);
    }
    if (tid < C) b1s[tid] = b1[tid];
    __syncthreads();

    // pool sums: thread = (patch p 0..3, channel pair cpair 0..31)
    {
        int p = tid >> 5, cpair = tid & 31;
        float s0 = 0.f, s1 = 0.f;
        #pragma unroll
        for (int u = 0; u < 16; ++u) {
            int px = (u >> 2) * 16 + p * 4 + (u & 3);   // row*16 + col
            uint32_t off = (uint32_t)(px * 128 + cpair * 4);
            __half2 hv = *(__half2*)(xb8 + swz128(off));
            float2 f = __half22float2(hv);
            s0 += f.x; s1 += f.y;
        }
        int n = b * NPB + i * PW + (w0 >> 2) + p;
        *(float2*)&g_pool[n * C + cpair * 2] = make_float2(s0, s1);
    }

    uint32_t xs_base = smem_u32(Xs);
    uint32_t ws_base = smem_u32(W1s);
    int li = lane >> 3, lr = lane & 7;

    float acc[8][4];
    #pragma unroll
    for (int ni = 0; ni < 8; ++ni)
        #pragma unroll
        for (int d = 0; d < 4; ++d) acc[ni][d] = 0.f;

    #pragma unroll
    for (int ki = 0; ki < 4; ++ki) {
        uint32_t a[4];
        {
            uint32_t off = (uint32_t)((wid * 16 + (li & 1) * 8 + lr) * 128
                                      + (li >> 1) * 16 + ki * 32);
            LDSM_X4(a[0], a[1], a[2], a[3], xs_base + swz128(off));
        }
        uint32_t bf[8][2];
        #pragma unroll
        for (int ci = 0; ci < 4; ++ci) {
            uint32_t off = (uint32_t)((ci * 16 + (li & 1) * 8 + lr) * 128
                                      + (li >> 1) * 16 + ki * 32);
            uint32_t t0, t1, t2, t3;
            LDSM_X4(t0, t1, t2, t3, ws_base + swz128(off));
            bf[ci * 2 + 0][0] = t0; bf[ci * 2 + 0][1] = t2;
            bf[ci * 2 + 1][0] = t1; bf[ci * 2 + 1][1] = t3;
        }
        #pragma unroll
        for (int ni = 0; ni < 8; ++ni)
            MMA16816(acc[ni], a, bf[ni]);
    }

    #pragma unroll
    for (int ni = 0; ni < 8; ++ni) {
        int c = ni * 8 + (lane & 3) * 2;
        float bv0 = b1s[c], bv1 = b1s[c + 1];
        #pragma unroll
        for (int h = 0; h < 2; ++h) {
            int px = wid * 16 + h * 8 + (lane >> 2);
            *(__half2*)&Os[px * 72 + c] =
                __floats2half2_rn(acc[ni][h * 2 + 0] + bv0,
                                  acc[ni][h * 2 + 1] + bv1);
        }
    }
    __syncthreads();

    char* ob8 = (char*)Os;
    for (int idx = tid; idx < 512; idx += 128) {
        int px = idx >> 3, seg = idx & 7;
        int h = h0 + (px >> 4), w = w0 + (px & 15);
        uint4 v = *(uint4*)(ob8 + px * 144 + seg * 16);
        *(uint4*)&g_tokensH[((size_t)(b * HW + h * W + w)) * C + seg * 8] = v;
    }
}

// ---------------------------------------------------------------------------
// Stage 2: params from pooled sums + w2->fp16 conversion WITH k-permutation:
// k_old = c*16 + pix  ->  k_new = pix*64 + c.
// ---------------------------------------------------------------------------
__global__ void params_kernel(const float* __restrict__ w_off,
                              const float* __restrict__ b_off,
                              const float* __restrict__ w_sc,
                              const float* __restrict__ b_sc,
                              const float* __restrict__ w2) {
    __shared__ float wofs[2 * C], wscs[2 * C];
    int tid = threadIdx.x;

    // w2 convert + permute (reads coalesced; writes scattered within 2KB row)
    {
        int gtid = blockIdx.x * 256 + tid;
        int nthreads = gridDim.x * 256;
        for (int idx = gtid; idx < E * KDIM; idx += nthreads) {
            int base = idx & ~1023;          // e*1024
            int r = idx & 1023;              // c*16 + pix
            int c = r >> 4, pix = r & 15;
            g_W2f[base | (pix << 6) | c] = __float2half_rn(w2[idx]);
        }
    }

    if (tid < 2 * C) {
        wofs[tid] = w_off[tid];
        wscs[tid] = w_sc[tid];
    }
    __syncthreads();

    int warp = tid >> 5, lane = tid & 31;
    int n = blockIdx.x * 8 + warp;
    int c0 = lane * 2;

    float2 pv = *(const float2*)&g_pool[n * C + c0];
    float g0 = pv.x * (1.0f / 16.0f);
    float g1 = pv.y * (1.0f / 16.0f);
    g0 = (g0 > 0.f) ? g0 : 0.01f * g0;
    g1 = (g1 > 0.f) ? g1 : 0.01f * g1;

    float aox = g0 * wofs[c0]     + g1 * wofs[c0 + 1];
    float aoy = g0 * wofs[C + c0] + g1 * wofs[C + c0 + 1];
    float asx = g0 * wscs[c0]     + g1 * wscs[c0 + 1];
    float asy = g0 * wscs[C + c0] + g1 * wscs[C + c0 + 1];

    #pragma unroll
    for (int s = 16; s >= 1; s >>= 1) {
        aox += __shfl_xor_sync(0xffffffffu, aox, s);
        aoy += __shfl_xor_sync(0xffffffffu, aoy, s);
        asx += __shfl_xor_sync(0xffffffffu, asx, s);
        asy += __shfl_xor_sync(0xffffffffu, asy, s);
    }
    if (lane == 0) {
        g_params[n * 4 + 0] = (aox + b_off[0]) * (1.0f / 56.0f);
        g_params[n * 4 + 1] = (aoy + b_off[1]) * (1.0f / 56.0f);
        g_params[n * 4 + 2] = asx + b_sc[0];
        g_params[n * 4 + 3] = asy + b_sc[1];
    }
}

// ---------------------------------------------------------------------------
// Stage 3: grid + bilinear gather -> V[n][k'] fp16, k' = pix*64 + c.
// Thread = 1 pixel x 32 channels: values are k'-CONTIGUOUS -> direct 4x
// STG.128, no SMEM bounce, no syncthreads, one pass.
// ---------------------------------------------------------------------------
__global__ void gather_kernel() {
    int n0 = blockIdx.x * 8;
    int tid = threadIdx.x;
    int slot = tid >> 1, half = tid & 1;
    int pl = slot >> 4, pix = slot & 15;
    int n = n0 + pl;
    int b = n / NPB; int r = n - b * NPB;
    int i = r / PW;  int j = r - i * PW;

    float offx = g_params[n * 4 + 0];
    float offy = g_params[n * 4 + 1];
    float scx  = g_params[n * 4 + 2];
    float scy  = g_params[n * 4 + 3];

    int py = pix >> 2, px = pix & 3;
    const float inv223 = 1.0f / 223.0f;
    float gx = (-1.0f + 2.0f * (4 * j + 1.5f) * inv223)
             + ((px - 1.5f) * 2.0f * inv223) * (1.0f + scx) + offx;
    float gy = (-1.0f + 2.0f * (4 * i + 1.5f) * inv223)
             + ((py - 1.5f) * 2.0f * inv223) * (1.0f + scy) + offy;
    float ix = (gx + 1.0f) * 0.5f * 223.0f;
    float iy = (gy + 1.0f) * 0.5f * 223.0f;

    float x0f = floorf(ix), y0f = floorf(iy);
    int x0 = (int)x0f, y0 = (int)y0f;
    float wx1 = ix - x0f, wx0 = 1.f - wx1;
    float wy1 = iy - y0f, wy0 = 1.f - wy1;

    float acc[32];
    #pragma unroll
    for (int q = 0; q < 32; ++q) acc[q] = 0.f;

    const __half* tb = g_tokensH + ((size_t)b * HW) * C + half * 32;
    int   xs[4] = { x0, x0 + 1, x0,     x0 + 1 };
    int   ys[4] = { y0, y0,     y0 + 1, y0 + 1 };
    float ws[4] = { wx0 * wy0, wx1 * wy0, wx0 * wy1, wx1 * wy1 };

    #pragma unroll
    for (int cr = 0; cr < 4; ++cr) {
        int xc = xs[cr], yc = ys[cr];
        if ((unsigned)xc < (unsigned)W && (unsigned)yc < (unsigned)H) {
            float wgt = ws[cr];
            const uint4* p4 = (const uint4*)(tb + ((size_t)yc * W + xc) * C);
            #pragma unroll
            for (int q = 0; q < 4; ++q) {        // 4 x 16B = 32 halfs
                uint4 t = p4[q];
                uint32_t wd[4] = { t.x, t.y, t.z, t.w };
                #pragma unroll
                for (int s = 0; s < 4; ++s) {
                    float2 f = __half22float2(*(__half2*)&wd[s]);
                    acc[q * 8 + s * 2 + 0] += wgt * f.x;
                    acc[q * 8 + s * 2 + 1] += wgt * f.y;
                }
            }
        }
    }

    // direct write: k' = pix*64 + half*32 + q  (contiguous 64B per thread)
    __half2 hv[16];
    #pragma unroll
    for (int q = 0; q < 16; ++q)
        hv[q] = __floats2half2_rn(acc[q * 2], acc[q * 2 + 1]);
    uint4* dst = (uint4*)&g_Vf[(size_t)n * KDIM + pix * 64 + half * 32];
    const uint4* src = (const uint4*)hv;
    #pragma unroll
    for (int q = 0; q < 4; ++q) dst[q] = src[q];
}

// ---------------------------------------------------------------------------
// Stage 4: fp16 mma.sync GEMM  out(768 x 25088) = W2(768x1024)*V + b2
// R14 measured-best config (at mma.sync roofline): BK=64, tile 128x128,
// warp 64x32, 3-stage cp.async, one barrier/chunk, 256 thr, occ 2.
// ---------------------------------------------------------------------------
#define BK 64
#define NCHUNK (KDIM / BK)          // 16
#define ROWB 144                    // 128B data + 16B pad per row
#define BUFB (128 * ROWB)           // 18432 B per operand buffer
#define STAGEB (2 * BUFB)           // A, B
#define NSTG 3
#define GEMM_SMEM (NSTG * STAGEB)   // 110592 B

__device__ __forceinline__ void load_chunk(uint32_t stage, int m0, int n0,
                                           int kc, int tid) {
    #pragma unroll
    for (int it = 0; it < 4; ++it) {
        int idx = tid + it * 256;               // 0..1023
        int row = idx >> 3, seg = idx & 7;
        uint32_t dst = (uint32_t)(row * ROWB + seg * 16);
        size_t ea = (((size_t)(m0 + row)) << 11) + (size_t)kc * 128 + seg * 16; // bytes
        size_t eb = (((size_t)(n0 + row)) << 11) + (size_t)kc * 128 + seg * 16;
        CP_ASYNC16(stage + dst,        (const char*)g_W2f + ea);
        CP_ASYNC16(stage + BUFB + dst, (const char*)g_Vf  + eb);
    }
}

__global__ void __launch_bounds__(256, 2) gemm_kernel(const float* __restrict__ b2,
                                                      float* __restrict__ out) {
    extern __shared__ char smem[];
    uint32_t sbase = smem_u32(smem);
    int tid = threadIdx.x;
    int wid = tid >> 5, lane = tid & 31;
    int m0 = blockIdx.x * 128;        // 6 m-tiles fastest (B-tile reuse in L2)
    int n0 = blockIdx.y * 128;        // 196 n-tiles
    int wm = (wid & 1) * 64;
    int wn = (wid >> 1) * 32;

    float acc[4][4][4];
    #pragma unroll
    for (int a = 0; a < 4; ++a)
        #pragma unroll
        for (int b = 0; b < 4; ++b)
            #pragma unroll
            for (int d = 0; d < 4; ++d) acc[a][b][d] = 0.f;

    int li = lane >> 3, lr = lane & 7;
    uint32_t a_off = (uint32_t)((wm + (li & 1) * 8 + lr) * ROWB + (li >> 1) * 16);
    uint32_t b_off = (uint32_t)((wn + (li & 1) * 8 + lr) * ROWB + (li >> 1) * 16);

    // prologue: chunks 0,1
    load_chunk(sbase + 0 * STAGEB, m0, n0, 0, tid); CP_COMMIT();
    load_chunk(sbase + 1 * STAGEB, m0, n0, 1, tid); CP_COMMIT();

    for (int kt = 0; kt < NCHUNK; ++kt) {
        if (kt < NCHUNK - 1) { CP_WAIT(1); } else { CP_WAIT(0); }
        __syncthreads();                 // single barrier per chunk

        int c = kt + 2;
        if (c < NCHUNK) {
            load_chunk(sbase + (uint32_t)(c % NSTG) * STAGEB, m0, n0, c, tid);
            CP_COMMIT();
        }

        uint32_t stg = sbase + (uint32_t)(kt % NSTG) * STAGEB;
        #pragma unroll
        for (int ks = 0; ks < 4; ++ks) {
            uint32_t koff = (uint32_t)(ks * 32);   // 16 k-elems = 32 bytes
            uint32_t ah[4][4], bh[4][2];
            #pragma unroll
            for (int mi = 0; mi < 4; ++mi) {
                uint32_t ad = stg + a_off + koff + (uint32_t)(mi * 16 * ROWB);
                LDSM_X4(ah[mi][0], ah[mi][1], ah[mi][2], ah[mi][3], ad);
            }
            #pragma unroll
            for (int nh = 0; nh < 2; ++nh) {
                uint32_t bd = stg + BUFB + b_off + koff + (uint32_t)(nh * 16 * ROWB);
                uint32_t t0, t1, t2, t3;
                LDSM_X4(t0, t1, t2, t3, bd);
                bh[nh * 2 + 0][0] = t0; bh[nh * 2 + 0][1] = t2;
                bh[nh * 2 + 1][0] = t1; bh[nh * 2 + 1][1] = t3;
            }
            #pragma unroll
            for (int mi = 0; mi < 4; ++mi)
                #pragma unroll
                for (int ni = 0; ni < 4; ++ni)
                    MMA16816(acc[mi][ni], ah[mi], bh[ni]);
        }
    }

    // epilogue
    #pragma unroll
    for (int mi = 0; mi < 4; ++mi) {
        #pragma unroll
        for (int hrow = 0; hrow < 2; ++hrow) {
            int m = m0 + wm + mi * 16 + hrow * 8 + (lane >> 2);
            float bias = b2[m];
            #pragma unroll
            for (int ni = 0; ni < 4; ++ni) {
                int n = n0 + wn + ni * 8 + (lane & 3) * 2;
                int bb = n / NPB;
                int rr = n - bb * NPB;
                float2 v;
                v.x = acc[mi][ni][hrow * 2 + 0] + bias;
                v.y = acc[mi][ni][hrow * 2 + 1] + bias;
                *(float2*)&out[(size_t)bb * (E * NPB) + (size_t)m * NPB + rr] = v;
            }
        }
    }
}

// ---------------------------------------------------------------------------
extern "C" void kernel_launch(void* const* d_in, const int* in_sizes, int n_in,
                              void* d_out, int out_size) {
    const float* x     = (const float*)d_in[0];
    const float* w1    = (const float*)d_in[1];
    const float* b1    = (const float*)d_in[2];
    const float* w2    = (const float*)d_in[3];
    const float* b2    = (const float*)d_in[4];
    const float* w_off = (const float*)d_in[5];
    const float* b_off = (const float*)d_in[6];
    const float* w_sc  = (const float*)d_in[7];
    const float* b_sc  = (const float*)d_in[8];
    float* out = (float*)d_out;

    cudaFuncSetAttribute(gemm_kernel, cudaFuncAttributeMaxDynamicSharedMemorySize,
                         GEMM_SMEM);

    tokens_kernel<<<dim3(W / 16, PH, BATCH), 128>>>(x, w1, b1);
    params_kernel<<<NP / 8, 256>>>(w_off, b_off, w_sc, b_sc, w2);
    gather_kernel<<<NP / 8, 256>>>();
    gemm_kernel<<<dim3(E / 128, NP / 128), 256, GEMM_SMEM>>>(b2, out);
}